// round 5
// baseline (speedup 1.0000x reference)
#include <cuda_runtime.h>
#include <cstdint>

#define NBINS   15
#define NCLASS  100
#define NKEYS   (NCLASS * NBINS)   // 1500
#define THREADS 384                // 12 warps
#define TILE_R  192                // rows per tile (= THREADS/2, one half-row per thread in pass 1)
#define ROWP    104                // padded row pitch in floats -> conflict-free LDS.128 both passes
#define GRID    152                // GB300: 152 SMs

// Dynamic smem layout (floats unless noted):
//   data0[TILE_R*ROWP] data1[TILE_R*ROWP] inv0[TILE_R] inv1[TILE_R] hist[NKEYS] lab0[TILE_R](int) lab1[TILE_R](int)
#define SMEM_BYTES ((2 * TILE_R * ROWP + 2 * TILE_R + NKEYS) * 4 + 2 * TILE_R * 4)

__device__ float g_D[NKEYS];   // signed sum(p - correct) per (class,bin); finalize re-zeroes -> replay-safe
__device__ int   g_cnt;        // block-done counter; last block resets

__device__ __forceinline__ uint32_t sm_u32(const void* p) {
    return (uint32_t)__cvta_generic_to_shared(p);
}
__device__ __forceinline__ void cp16(void* s, const void* g) {
    asm volatile("cp.async.cg.shared.global [%0], [%1], 16;" :: "r"(sm_u32(s)), "l"(g));
}
__device__ __forceinline__ void cp4(void* s, const void* g) {
    asm volatile("cp.async.ca.shared.global [%0], [%1], 4;" :: "r"(sm_u32(s)), "l"(g));
}
__device__ __forceinline__ void cp_commit() { asm volatile("cp.async.commit_group;"); }
__device__ __forceinline__ void cp_wait1()  { asm volatile("cp.async.wait_group 1;"); }

__device__ __forceinline__ void prefetch_tile(const float* __restrict__ logits,
                                              const int* __restrict__ labels,
                                              int N, int n_tiles, int tile,
                                              float* d, int* lb) {
    if (tile >= n_tiles) return;
    const long base = (long)tile * TILE_R;
    const int  rows = min(TILE_R, N - (int)base);
    const float4* g = (const float4*)logits + base * (NCLASS / 4);
    const int nf4 = rows * (NCLASS / 4);
    for (int i = threadIdx.x; i < nf4; i += THREADS) {
        const int r  = i / 25;            // 25 float4 per row
        const int c4 = i - r * 25;
        cp16(d + r * ROWP + c4 * 4, g + i);
    }
    for (int i = threadIdx.x; i < rows; i += THREADS)
        cp4(lb + i, labels + base + i);
}

__global__ void __launch_bounds__(THREADS, 1)
ece_fused(const float* __restrict__ logits, const int* __restrict__ labels,
          float* __restrict__ out, int out_size, int N)
{
    extern __shared__ float sm[];
    float* data0 = sm;
    float* data1 = data0 + TILE_R * ROWP;
    float* inv0  = data1 + TILE_R * ROWP;
    float* inv1  = inv0 + TILE_R;
    float* hist  = inv1 + TILE_R;                    // NKEYS
    int*   lab0  = (int*)(hist + NKEYS);
    int*   lab1  = lab0 + TILE_R;

    const int tid  = threadIdx.x;
    const int warp = tid >> 5;
    const int lane = tid & 31;
    const bool owner = (lane < 25);                  // 25 lanes * 4 classes = 100
    const int c0 = lane * 4;

    for (int i = tid; i < NKEYS; i += THREADS) hist[i] = 0.0f;
    // (ordered before first use by the syncthreads inside the tile loop)

    float acc0 = 0.f, acc1 = 0.f, acc2 = 0.f, acc3 = 0.f;

    const int n_tiles = (N + TILE_R - 1) / TILE_R;

    int t = blockIdx.x;
    prefetch_tile(logits, labels, N, n_tiles, t, data0, lab0);
    cp_commit();

    int p = 0;
    for (; t < n_tiles; t += gridDim.x) {
        prefetch_tile(logits, labels, N, n_tiles, t + gridDim.x,
                      p ? data0 : data1, p ? lab0 : lab1);
        cp_commit();
        cp_wait1();                                   // tile t resident
        __syncthreads();

        float* D  = p ? data1 : data0;
        float* IV = p ? inv1 : inv0;
        int*   LB = p ? lab1 : lab0;
        const int rows = min(TILE_R, N - t * TILE_R);

        // ---- pass 1: exp in place + row sums (thread-per-half-row, no SHFL trees)
        {
            const int r = tid >> 1, h = tid & 1;
            float s = 0.f;
            if (r < rows) {
                float4* rp = (float4*)(D + r * ROWP) + (h ? 13 : 0);
                const int n4 = h ? 12 : 13;
                #pragma unroll
                for (int k = 0; k < 13; ++k) {
                    if (k < n4) {
                        float4 v = rp[k];
                        v.x = __expf(v.x); v.y = __expf(v.y);
                        v.z = __expf(v.z); v.w = __expf(v.w);
                        rp[k] = v;
                        s += (v.x + v.y) + (v.z + v.w);
                    }
                }
            }
            s += __shfl_xor_sync(0xffffffffu, s, 1);  // combine the two halves
            if (r < rows && h == 0) IV[r] = 1.0f / s;
        }
        __syncthreads();

        // ---- pass 2: warp-per-row binning (lane owns 4 fixed classes)
        {
            const int r1 = min(warp * 16 + 16, rows);
            for (int r = warp * 16; r < r1; ++r) {
                const float iv  = IV[r];
                const int   lab = LB[r];
                if (owner) {
                    const float4 ev = *((const float4*)(D + r * ROWP + c0));
                    #pragma unroll
                    for (int j = 0; j < 4; ++j) {
                        const float e = (j == 0) ? ev.x : (j == 1) ? ev.y
                                       : (j == 2) ? ev.z : ev.w;
                        const float pp  = e * iv;                 // p > 0 always
                        const float t15 = pp * 15.0f;
                        const float contrib = pp - ((lab == c0 + j) ? 1.0f : 0.0f);
                        if (t15 <= 1.0f) {                        // bin 0 fast path (~99%)
                            if      (j == 0) acc0 += contrib;
                            else if (j == 1) acc1 += contrib;
                            else if (j == 2) acc2 += contrib;
                            else             acc3 += contrib;
                        } else {                                  // bins (l,u]: b=ceil(p*15)-1
                            int b = __float2int_ru(t15) - 1;
                            b = min(b, NBINS - 1);
                            atomicAdd(&hist[(c0 + j) * NBINS + b], contrib);
                        }
                    }
                }
            }
        }
        __syncthreads();                               // protect buffer before overwrite
        p ^= 1;
    }

    // ---- flush register accumulators, then block totals to global
    if (owner) {
        atomicAdd(&hist[(c0 + 0) * NBINS], acc0);
        atomicAdd(&hist[(c0 + 1) * NBINS], acc1);
        atomicAdd(&hist[(c0 + 2) * NBINS], acc2);
        atomicAdd(&hist[(c0 + 3) * NBINS], acc3);
    }
    __syncthreads();
    for (int i = tid; i < NKEYS; i += THREADS) {
        const float h = hist[i];
        if (h != 0.0f) atomicAdd(&g_D[i], h);
    }

    // ---- last-block finalize
    __shared__ bool isLast;
    __shared__ float red[128];
    if (tid == 0) {
        __threadfence();
        isLast = (atomicAdd(&g_cnt, 1) == (int)gridDim.x - 1);
    }
    __syncthreads();
    if (!isLast) return;

    float per = 0.f;
    if (tid < NCLASS) {
        #pragma unroll
        for (int b = 0; b < NBINS; ++b) {
            const int k = tid * NBINS + b;
            per += fabsf(__ldcg(&g_D[k]));
            g_D[k] = 0.0f;                             // reset for next call/replay
        }
        per /= (float)N;
    }
    if (tid < 128) red[tid] = (tid < NCLASS) ? per : 0.f;
    __syncthreads();
    #pragma unroll
    for (int o = 64; o > 0; o >>= 1) {
        if (tid < o) red[tid] += red[tid + o];
        __syncthreads();
    }
    const float sce = red[0] / (float)NCLASS;
    if (tid == 0) g_cnt = 0;

    if (out_size >= NCLASS + 1) {
        if (tid == 0) out[0] = sce;
        if (tid < NCLASS) out[1 + tid] = per;
    } else if (out_size == NCLASS) {
        if (tid < NCLASS) out[tid] = per;
    } else if (tid == 0 && out_size >= 1) {
        out[0] = sce;
    }
}

extern "C" void kernel_launch(void* const* d_in, const int* in_sizes, int n_in,
                              void* d_out, int out_size)
{
    const float* logits = (const float*)d_in[0];
    const int*   labels = (const int*)d_in[1];
    const int N = in_sizes[1];   // number of rows

    cudaFuncSetAttribute(ece_fused, cudaFuncAttributeMaxDynamicSharedMemorySize, SMEM_BYTES);
    ece_fused<<<GRID, THREADS, SMEM_BYTES>>>(logits, labels, (float*)d_out, out_size, N);
}

// round 9
// speedup vs baseline: 1.0736x; 1.0736x over previous
#include <cuda_runtime.h>
#include <cstdint>

#define NBINS   15
#define NCLASS  100
#define NKEYS   (NCLASS * NBINS)   // 1500
#define THREADS 256                // 8 warps per block
#define WPB     8
#define CHUNK   8                  // rows per warp-chunk (L1-resident between passes)
#define GRID    760                // 152 SMs * 5 blocks, persistent

__device__ float g_D[NKEYS];   // signed sum(p - correct); finalize re-zeroes -> replay-safe
__device__ int   g_cnt;        // block-done counter; last block resets

__global__ void __launch_bounds__(THREADS, 5)
ece_fused(const float* __restrict__ logits, const int* __restrict__ labels,
          float* __restrict__ out, int out_size, int N)
{
    __shared__ float hist[NKEYS];
    for (int i = threadIdx.x; i < NKEYS; i += THREADS) hist[i] = 0.0f;
    __syncthreads();

    const int  warp  = threadIdx.x >> 5;
    const int  lane  = threadIdx.x & 31;
    const bool owner = (lane < 25);            // 25 lanes * 4 classes = 100
    const int  c0    = lane * 4;

    const int gwarp   = blockIdx.x * WPB + warp;
    const int nwarps  = gridDim.x * WPB;
    const int nchunks = (N + CHUNK - 1) / CHUNK;

    // register accumulators for bin 0 of this lane's 4 classes (~99% of mass)
    float acc0 = 0.f, acc1 = 0.f, acc2 = 0.f, acc3 = 0.f;

    for (int ch = gwarp; ch < nchunks; ch += nwarps) {
        const int base = ch * CHUNK;
        const int rows = min(CHUNK, N - base);

        // labels for this chunk: lane r holds label of row base+r
        int labq = 0;
        if (lane < rows) labq = labels[base + lane];

        // ---- pass 1: coalesced loads + exp + per-row butterfly sum ----
        float s_arr[CHUNK];
        #pragma unroll
        for (int r = 0; r < CHUNK; ++r) {
            float partial = 0.f;
            if (r < rows && owner) {
                const float4 v = *reinterpret_cast<const float4*>(
                    logits + (size_t)(base + r) * NCLASS + c0);
                partial = (__expf(v.x) + __expf(v.y)) + (__expf(v.z) + __expf(v.w));
            }
            #pragma unroll
            for (int o = 16; o; o >>= 1)
                partial += __shfl_xor_sync(0xffffffffu, partial, o);
            s_arr[r] = partial;               // full row sum, in every lane
        }

        // ---- pass 2: re-load (L1 hit), recompute exp, bin ----
        #pragma unroll
        for (int r = 0; r < CHUNK; ++r) {
            if (r < rows) {
                const int   lab = __shfl_sync(0xffffffffu, labq, r);
                const float s   = s_arr[r];
                const float iv  = __fdividef(1.0f, s);
                const float s15 = s * (1.0f / 15.0f);   // fast test: e <= s/15  <=>  p <= 1/15
                if (owner) {
                    const float4 v = *reinterpret_cast<const float4*>(
                        logits + (size_t)(base + r) * NCLASS + c0);
                    const float e0 = __expf(v.x), e1 = __expf(v.y);
                    const float e2 = __expf(v.z), e3 = __expf(v.w);
                    #pragma unroll
                    for (int j = 0; j < 4; ++j) {
                        const float e = (j == 0) ? e0 : (j == 1) ? e1 : (j == 2) ? e2 : e3;
                        const float p = e * iv;                    // p > 0 always (no exp underflow here)
                        float val = p;
                        if (c0 + j == lab) val -= 1.0f;            // exactly one per row
                        if (e <= s15) {                            // bin 0 fast path (~99%)
                            if      (j == 0) acc0 += val;
                            else if (j == 1) acc1 += val;
                            else if (j == 2) acc2 += val;
                            else             acc3 += val;
                        } else {                                   // bins (l,u]: b = ceil(p*15)-1
                            int b = __float2int_ru(p * 15.0f) - 1;
                            b = min(b, NBINS - 1);
                            atomicAdd(&hist[(c0 + j) * NBINS + b], val);
                        }
                    }
                }
            }
        }
    }

    // ---- flush register accumulators, then block totals to global ----
    if (owner) {
        atomicAdd(&hist[(c0 + 0) * NBINS], acc0);
        atomicAdd(&hist[(c0 + 1) * NBINS], acc1);
        atomicAdd(&hist[(c0 + 2) * NBINS], acc2);
        atomicAdd(&hist[(c0 + 3) * NBINS], acc3);
    }
    __syncthreads();
    for (int i = threadIdx.x; i < NKEYS; i += THREADS) {
        const float h = hist[i];
        if (h != 0.0f) atomicAdd(&g_D[i], h);
    }

    // ---- last-block finalize ----
    __shared__ bool  isLast;
    __shared__ float red[128];
    if (threadIdx.x == 0) {
        __threadfence();
        isLast = (atomicAdd(&g_cnt, 1) == (int)gridDim.x - 1);
    }
    __syncthreads();
    if (!isLast) return;

    const int tid = threadIdx.x;
    float per = 0.f;
    if (tid < NCLASS) {
        #pragma unroll
        for (int b = 0; b < NBINS; ++b) {
            const int k = tid * NBINS + b;
            per += fabsf(__ldcg(&g_D[k]));
            g_D[k] = 0.0f;                   // reset for next call / graph replay
        }
        per /= (float)N;
    }
    if (tid < 128) red[tid] = (tid < NCLASS) ? per : 0.f;
    __syncthreads();
    #pragma unroll
    for (int o = 64; o > 0; o >>= 1) {
        if (tid < o && tid < 128) red[tid] += red[tid + o];
        __syncthreads();
    }
    const float sce = red[0] / (float)NCLASS;
    if (tid == 0) g_cnt = 0;

    if (out_size >= NCLASS + 1) {
        if (tid == 0) out[0] = sce;
        if (tid < NCLASS) out[1 + tid] = per;
    } else if (out_size == NCLASS) {
        if (tid < NCLASS) out[tid] = per;
    } else if (tid == 0 && out_size >= 1) {
        out[0] = sce;
    }
}

extern "C" void kernel_launch(void* const* d_in, const int* in_sizes, int n_in,
                              void* d_out, int out_size)
{
    const float* logits = (const float*)d_in[0];
    const int*   labels = (const int*)d_in[1];
    const int N = in_sizes[1];   // number of rows

    ece_fused<<<GRID, THREADS>>>(logits, labels, (float*)d_out, out_size, N);
}

// round 10
// speedup vs baseline: 1.2430x; 1.1577x over previous
#include <cuda_runtime.h>
#include <cstdint>

#define NBINS   15
#define NCLASS  100
#define NKEYS   (NCLASS * NBINS)   // 1500
#define THREADS 256                // 8 warps per block
#define WPB     8
#define CHUNK   2                  // rows per warp iteration (MLP=2)
#define GRID    760                // 152 SMs * 5 blocks, persistent

__device__ float g_D[NKEYS];   // signed sum(p - correct); finalize re-zeroes -> replay-safe
__device__ int   g_cnt;        // block-done counter; last block resets

__global__ void __launch_bounds__(THREADS, 5)
ece_fused(const float* __restrict__ logits, const int* __restrict__ labels,
          float* __restrict__ out, int out_size, int N)
{
    __shared__ float hist[NKEYS];
    for (int i = threadIdx.x; i < NKEYS; i += THREADS) hist[i] = 0.0f;
    __syncthreads();

    const int  warp  = threadIdx.x >> 5;
    const int  lane  = threadIdx.x & 31;
    const bool owner = (lane < 25);            // 25 lanes * 4 classes = 100
    const int  c0    = lane * 4;

    const int gwarp   = blockIdx.x * WPB + warp;
    const int nwarps  = gridDim.x * WPB;
    const int nchunks = (N + CHUNK - 1) / CHUNK;

    // bin-0 register accumulators for this lane's 4 classes (~99% of all mass)
    float acc0 = 0.f, acc1 = 0.f, acc2 = 0.f, acc3 = 0.f;

    for (int ch = gwarp; ch < nchunks; ch += nwarps) {
        const int base = ch * CHUNK;

        // ---- issue both rows' loads first (MLP) ----
        float4 v[CHUNK];
        int    lb[CHUNK];
        #pragma unroll
        for (int r = 0; r < CHUNK; ++r) {
            const int row = base + r;
            if (row < N) {                               // warp-uniform
                lb[r] = labels[row];
                if (owner)
                    v[r] = *reinterpret_cast<const float4*>(
                        logits + (size_t)row * NCLASS + c0);
                else
                    v[r] = make_float4(0.f, 0.f, 0.f, 0.f);
            } else {
                lb[r] = -1;
                v[r] = make_float4(0.f, 0.f, 0.f, 0.f);
            }
        }

        #pragma unroll
        for (int r = 0; r < CHUNK; ++r) {
            const int row = base + r;
            if (row >= N) break;                          // warp-uniform
            const int lab = lb[r];

            // exp (kept in registers for the whole row lifetime)
            float e0 = 0.f, e1 = 0.f, e2 = 0.f, e3 = 0.f;
            if (owner) {
                e0 = __expf(v[r].x); e1 = __expf(v[r].y);
                e2 = __expf(v[r].z); e3 = __expf(v[r].w);
            }
            float s = (e0 + e1) + (e2 + e3);
            #pragma unroll
            for (int o = 16; o; o >>= 1)
                s += __shfl_xor_sync(0xffffffffu, s, o);

            const float iv  = __fdividef(1.0f, s);
            const float s15 = s * (1.0f / 15.0f);        // e <= s/15  <=>  p <= 1/15 (bin 0)

            // ---- branch-free fast path: acc += e*iv, minus 1 if (bin0 && label) ----
            const bool le0 = (e0 <= s15), le1 = (e1 <= s15),
                       le2 = (e2 <= s15), le3 = (e3 <= s15);
            acc0 += e0 * iv - ((le0 && lab == c0 + 0) ? 1.0f : 0.0f);
            acc1 += e1 * iv - ((le1 && lab == c0 + 1) ? 1.0f : 0.0f);
            acc2 += e2 * iv - ((le2 && lab == c0 + 2) ? 1.0f : 0.0f);
            acc3 += e3 * iv - ((le3 && lab == c0 + 3) ? 1.0f : 0.0f);

            // ---- rare exceeder path: move contribution from bin-0 reg to hist[b] ----
            const bool anyexc = !(le0 & le1 & le2 & le3);
            if (__ballot_sync(0xffffffffu, anyexc)) {     // ~55% of rows enter; ~0.8 elems/row
                #pragma unroll
                for (int j = 0; j < 4; ++j) {
                    const float e = (j == 0) ? e0 : (j == 1) ? e1 : (j == 2) ? e2 : e3;
                    if (e > s15) {
                        const float p = e * iv;
                        int b = __float2int_ru(p * 15.0f) - 1;   // bins (l,u]
                        b = max(0, min(b, NBINS - 1));
                        const float w = p - ((lab == c0 + j) ? 1.0f : 0.0f);
                        atomicAdd(&hist[(c0 + j) * NBINS + b], w);
                        // remove the p we optimistically put into the bin-0 register
                        if      (j == 0) acc0 -= p;
                        else if (j == 1) acc1 -= p;
                        else if (j == 2) acc2 -= p;
                        else             acc3 -= p;
                    }
                }
            }
        }
    }

    // ---- flush register accumulators, then block totals to global ----
    if (owner) {
        atomicAdd(&hist[(c0 + 0) * NBINS], acc0);
        atomicAdd(&hist[(c0 + 1) * NBINS], acc1);
        atomicAdd(&hist[(c0 + 2) * NBINS], acc2);
        atomicAdd(&hist[(c0 + 3) * NBINS], acc3);
    }
    __syncthreads();
    for (int i = threadIdx.x; i < NKEYS; i += THREADS) {
        const float h = hist[i];
        if (h != 0.0f) atomicAdd(&g_D[i], h);
    }

    // ---- last-block finalize ----
    __shared__ bool  isLast;
    __shared__ float red[128];
    if (threadIdx.x == 0) {
        __threadfence();
        isLast = (atomicAdd(&g_cnt, 1) == (int)gridDim.x - 1);
    }
    __syncthreads();
    if (!isLast) return;

    const int tid = threadIdx.x;
    float per = 0.f;
    if (tid < NCLASS) {
        #pragma unroll
        for (int b = 0; b < NBINS; ++b) {
            const int k = tid * NBINS + b;
            per += fabsf(__ldcg(&g_D[k]));
            g_D[k] = 0.0f;                   // reset for next call / graph replay
        }
        per /= (float)N;
    }
    if (tid < 128) red[tid] = (tid < NCLASS) ? per : 0.f;
    __syncthreads();
    #pragma unroll
    for (int o = 64; o > 0; o >>= 1) {
        if (tid < o && tid < 128) red[tid] += red[tid + o];
        __syncthreads();
    }
    const float sce = red[0] / (float)NCLASS;
    if (tid == 0) g_cnt = 0;

    if (out_size >= NCLASS + 1) {
        if (tid == 0) out[0] = sce;
        if (tid < NCLASS) out[1 + tid] = per;
    } else if (out_size == NCLASS) {
        if (tid < NCLASS) out[tid] = per;
    } else if (tid == 0 && out_size >= 1) {
        out[0] = sce;
    }
}

extern "C" void kernel_launch(void* const* d_in, const int* in_sizes, int n_in,
                              void* d_out, int out_size)
{
    const float* logits = (const float*)d_in[0];
    const int*   labels = (const int*)d_in[1];
    const int N = in_sizes[1];   // number of rows

    ece_fused<<<GRID, THREADS>>>(logits, labels, (float*)d_out, out_size, N);
}

// round 12
// speedup vs baseline: 1.3251x; 1.0661x over previous
#include <cuda_runtime.h>
#include <cstdint>

#define NBINS   15
#define NCLASS  100
#define NKEYS   (NCLASS * NBINS)   // 1500
#define THREADS 256                // 8 warps per block
#define WPB     8
#define CHUNK   2                  // rows per warp iteration (MLP=2)
#define GRID    760                // 152 SMs * 5 blocks, persistent

__device__ float g_D[NKEYS];   // signed sum(p - correct); finalize re-zeroes -> replay-safe
__device__ int   g_cnt;        // block-done counter; last block resets

__global__ void __launch_bounds__(THREADS, 5)
ece_fused(const float* __restrict__ logits, const int* __restrict__ labels,
          float* __restrict__ out, int out_size, int N)
{
    __shared__ float hist[NKEYS];
    for (int i = threadIdx.x; i < NKEYS; i += THREADS) hist[i] = 0.0f;
    __syncthreads();

    const int  warp  = threadIdx.x >> 5;
    const int  lane  = threadIdx.x & 31;
    const bool owner = (lane < 25);            // 25 lanes * 4 classes = 100
    const int  c0    = lane * 4;

    const int gwarp   = blockIdx.x * WPB + warp;
    const int nwarps  = gridDim.x * WPB;
    const int nchunks = (N + CHUNK - 1) / CHUNK;

    // bin-0 register accumulators for this lane's 4 classes (~99% of all mass)
    float acc0 = 0.f, acc1 = 0.f, acc2 = 0.f, acc3 = 0.f;
    // packed per-class label counts (byte j = #rows whose label == c0+j), applied at flush
    unsigned int cnt = 0;

    for (int ch = gwarp; ch < nchunks; ch += nwarps) {
        const int base = ch * CHUNK;

        // ---- issue both rows' loads first (MLP) ----
        float4 v[CHUNK];
        int    lb[CHUNK];
        #pragma unroll
        for (int r = 0; r < CHUNK; ++r) {
            const int row = base + r;
            if (row < N) {                               // warp-uniform
                lb[r] = labels[row];
                if (owner)
                    v[r] = *reinterpret_cast<const float4*>(
                        logits + (size_t)row * NCLASS + c0);
                else
                    v[r] = make_float4(0.f, 0.f, 0.f, 0.f);
            } else {
                lb[r] = -1;
                v[r] = make_float4(0.f, 0.f, 0.f, 0.f);
            }
        }

        #pragma unroll
        for (int r = 0; r < CHUNK; ++r) {
            const int row = base + r;
            if (row >= N) break;                          // warp-uniform
            const int lab = lb[r];

            const float e0 = owner ? __expf(v[r].x) : 0.f;
            const float e1 = owner ? __expf(v[r].y) : 0.f;
            const float e2 = owner ? __expf(v[r].z) : 0.f;
            const float e3 = owner ? __expf(v[r].w) : 0.f;

            float s = (e0 + e1) + (e2 + e3);
            #pragma unroll
            for (int o = 16; o; o >>= 1)
                s += __shfl_xor_sync(0xffffffffu, s, o);

            const float iv  = __fdividef(1.0f, s);
            const float s15 = s * (1.0f / 15.0f);         // e <= s/15 <=> p <= 1/15 (bin 0)

            // ---- fast path: 4 bare FFMAs ----
            acc0 = __fmaf_rn(e0, iv, acc0);
            acc1 = __fmaf_rn(e1, iv, acc1);
            acc2 = __fmaf_rn(e2, iv, acc2);
            acc3 = __fmaf_rn(e3, iv, acc3);

            // label ownership: one lane per row; byte-packed count
            const unsigned int j = (unsigned int)(lab - c0);
            if (j < 4u) cnt += 1u << (8u * j);

            // ---- exceeder path (rare): max-tree test, per-lane branch ----
            const float emax = fmaxf(fmaxf(e0, e1), fmaxf(e2, e3));
            if (emax > s15) {
                #pragma unroll
                for (int k = 0; k < 4; ++k) {
                    const float e = (k == 0) ? e0 : (k == 1) ? e1 : (k == 2) ? e2 : e3;
                    if (e > s15) {
                        const float p = e * iv;
                        int b = __float2int_ru(p * 15.0f) - 1;   // bins (l,u]; e>s15 -> b>=1
                        b = min(b, NBINS - 1);
                        const bool labm = (lab == c0 + k);
                        const float w = p - (labm ? 1.0f : 0.0f);
                        atomicAdd(&hist[(c0 + k) * NBINS + b], w);
                        // undo optimistic bin-0 bookkeeping for this element
                        if      (k == 0) acc0 -= p;
                        else if (k == 1) acc1 -= p;
                        else if (k == 2) acc2 -= p;
                        else             acc3 -= p;
                        if (labm) cnt -= 1u << (8u * k);
                    }
                }
            }
        }
    }

    // ---- flush: apply packed label corrections, then block totals to global ----
    if (owner) {
        acc0 -= (float)( cnt         & 0xffu);
        acc1 -= (float)((cnt >>  8u) & 0xffu);
        acc2 -= (float)((cnt >> 16u) & 0xffu);
        acc3 -= (float)((cnt >> 24u) & 0xffu);
        atomicAdd(&hist[(c0 + 0) * NBINS], acc0);
        atomicAdd(&hist[(c0 + 1) * NBINS], acc1);
        atomicAdd(&hist[(c0 + 2) * NBINS], acc2);
        atomicAdd(&hist[(c0 + 3) * NBINS], acc3);
    }
    __syncthreads();
    for (int i = threadIdx.x; i < NKEYS; i += THREADS) {
        const float h = hist[i];
        if (h != 0.0f) atomicAdd(&g_D[i], h);
    }

    // ---- last-block finalize ----
    __shared__ bool  isLast;
    __shared__ float red[128];
    if (threadIdx.x == 0) {
        __threadfence();
        isLast = (atomicAdd(&g_cnt, 1) == (int)gridDim.x - 1);
    }
    __syncthreads();
    if (!isLast) return;

    const int tid = threadIdx.x;
    float per = 0.f;
    if (tid < NCLASS) {
        #pragma unroll
        for (int b = 0; b < NBINS; ++b) {
            const int k = tid * NBINS + b;
            per += fabsf(__ldcg(&g_D[k]));
            g_D[k] = 0.0f;                   // reset for next call / graph replay
        }
        per /= (float)N;
    }
    if (tid < 128) red[tid] = (tid < NCLASS) ? per : 0.f;
    __syncthreads();
    #pragma unroll
    for (int o = 64; o > 0; o >>= 1) {
        if (tid < o && tid < 128) red[tid] += red[tid + o];
        __syncthreads();
    }
    const float sce = red[0] / (float)NCLASS;
    if (tid == 0) g_cnt = 0;

    if (out_size >= NCLASS + 1) {
        if (tid == 0) out[0] = sce;
        if (tid < NCLASS) out[1 + tid] = per;
    } else if (out_size == NCLASS) {
        if (tid < NCLASS) out[tid] = per;
    } else if (tid == 0 && out_size >= 1) {
        out[0] = sce;
    }
}

extern "C" void kernel_launch(void* const* d_in, const int* in_sizes, int n_in,
                              void* d_out, int out_size)
{
    const float* logits = (const float*)d_in[0];
    const int*   labels = (const int*)d_in[1];
    const int N = in_sizes[1];   // number of rows

    ece_fused<<<GRID, THREADS>>>(logits, labels, (float*)d_out, out_size, N);
}